// round 8
// baseline (speedup 1.0000x reference)
#include <cuda_runtime.h>
#include <cuda_bf16.h>
#include <cstdint>

// NeRF raw2outputs. R8: block-level cp.async.bulk staging of raw+z into smem
// (decouples memory-level-parallelism from the register file). 8 rays/block,
// one warp per ray. z in smem kills the neighbor-shuffle for dists. Weights
// stored with __stcs. Maps as before.
//
// Output layout (tuple flattened in order), N = num rays:
//   [0 , 3N)     rgb_map   [N,3]
//   [3N, 4N)     disp_map  [N,1]
//   [4N, 5N)     acc_map   [N,1]
//   [5N, 197N)   weights   [N,192]
//   [197N, 198N) depth_map [N,1]

#define FULL 0xffffffffu
#define NSAMP 192
#define NCHUNK 6
#define RAYS_PER_BLK 8
#define INF_DIST 1e10f

__device__ __forceinline__ uint32_t smem_u32(const void* p) {
    uint32_t a;
    asm("{ .reg .u64 t; cvta.to.shared.u64 t, %1; cvt.u32.u64 %0, t; }"
        : "=r"(a) : "l"(p));
    return a;
}

__device__ __forceinline__ float fast_sigmoid(float x) {
    float t;
    asm("tanh.approx.f32 %0, %1;" : "=f"(t) : "f"(0.5f * x));
    return fmaf(0.5f, t, 0.5f);
}

__global__ __launch_bounds__(256)
void nerf_render_kernel(const float4* __restrict__ raw4,
                        const float*  __restrict__ z_vals,
                        const float*  __restrict__ rays_d,
                        float* __restrict__ out,
                        int N)
{
    __shared__ __align__(128) float4 s_raw[RAYS_PER_BLK * NSAMP];      // 24576 B
    __shared__ __align__(128) float  s_z[RAYS_PER_BLK * NSAMP];        //  6144 B
    __shared__ __align__(8)   unsigned long long s_mbar;

    const int warp = threadIdx.x >> 5;
    const int lane = threadIdx.x & 31;
    const int ray0 = blockIdx.x * RAYS_PER_BLK;
    const int nrays = min(RAYS_PER_BLK, N - ray0);          // >=1 by grid sizing

    const uint32_t mbar = smem_u32(&s_mbar);

    if (threadIdx.x == 0) {
        asm volatile("mbarrier.init.shared.b64 [%0], 1;" :: "r"(mbar) : "memory");
        asm volatile("fence.proxy.async.shared::cta;" ::: "memory");
    }
    __syncthreads();

    if (threadIdx.x == 0) {
        const uint32_t raw_bytes = (uint32_t)nrays * NSAMP * 16u;
        const uint32_t z_bytes   = (uint32_t)nrays * NSAMP * 4u;
        asm volatile("mbarrier.arrive.expect_tx.shared.b64 _, [%0], %1;"
                     :: "r"(mbar), "r"(raw_bytes + z_bytes) : "memory");
        asm volatile("cp.async.bulk.shared::cta.global.mbarrier::complete_tx::bytes"
                     " [%0], [%1], %2, [%3];"
                     :: "r"(smem_u32(s_raw)),
                        "l"(raw4 + (long)ray0 * NSAMP),
                        "r"(raw_bytes), "r"(mbar) : "memory");
        asm volatile("cp.async.bulk.shared::cta.global.mbarrier::complete_tx::bytes"
                     " [%0], [%1], %2, [%3];"
                     :: "r"(smem_u32(s_z)),
                        "l"(z_vals + (long)ray0 * NSAMP),
                        "r"(z_bytes), "r"(mbar) : "memory");
    }

    // overlap: load ray direction while TMA is in flight
    const int ray = ray0 + warp;
    float nrm = 0.f;
    if (ray < N) {
        const float dx = rays_d[3 * ray + 0];
        const float dy = rays_d[3 * ray + 1];
        const float dz = rays_d[3 * ray + 2];
        nrm = sqrtf(dx * dx + dy * dy + dz * dz);
    }

    // wait for the bulk copy (acquire)
    {
        uint32_t done;
        asm volatile(
            "{\n .reg .pred p;\n"
            " mbarrier.try_wait.parity.acquire.cta.shared::cta.b64 p, [%1], 0;\n"
            " selp.b32 %0, 1, 0, p;\n}"
            : "=r"(done) : "r"(mbar) : "memory");
        if (!done) {
            asm volatile(
                "{\n .reg .pred P1;\n"
                "W%=:\n"
                " mbarrier.try_wait.parity.acquire.cta.shared::cta.b64 P1, [%0], 0, 0x989680;\n"
                " @P1 bra.uni D%=;\n"
                " bra.uni W%=;\n"
                "D%=:\n}"
                :: "r"(mbar) : "memory");
        }
    }

    if (ray >= N) return;   // after barrier participation

    const int sbase = warp * NSAMP;
    const long base = (long)ray * NSAMP;

    // ---- per-sample alpha, t (z dists straight from smem; no shuffles) ----
    float alpha[NCHUNK], p[NCHUNK];
#pragma unroll
    for (int c = 0; c < NCHUNK; ++c) {
        const int i = c * 32 + lane;
        const float z  = s_z[sbase + i];
        const float zn = (i == NSAMP - 1) ? INF_DIST : s_z[sbase + i + 1];
        const float dist = (zn - z) * nrm;       // (inf-z)*nrm still inf-scale
        const float sigma = fmaxf(s_raw[sbase + i].w, 0.f);
        alpha[c] = 1.f - __expf(-sigma * ((i == NSAMP - 1) ? INF_DIST : dist));
        p[c] = 1.f - alpha[c] + 1e-10f;
    }

    // ---- 6 interleaved inclusive product scans ----
#pragma unroll
    for (int off = 1; off < 32; off <<= 1) {
#pragma unroll
        for (int c = 0; c < NCHUNK; ++c) {
            const float u = __shfl_up_sync(FULL, p[c], off);
            if (lane >= off) p[c] *= u;
        }
    }

    float exc[NCHUNK], tot[NCHUNK];
#pragma unroll
    for (int c = 0; c < NCHUNK; ++c) {
        exc[c] = __shfl_up_sync(FULL, p[c], 1);
        if (lane == 0) exc[c] = 1.f;
        tot[c] = __shfl_sync(FULL, p[c], 31);
    }

    float carry[NCHUNK];
    carry[0] = 1.f;
#pragma unroll
    for (int c = 1; c < NCHUNK; ++c)
        carry[c] = carry[c - 1] * tot[c - 1];

    // ---- weights, accumulation, streaming stores (rgb re-read from smem) ----
    float* __restrict__ wout = out + (long)5 * N;
    float r_sum = 0.f, g_sum = 0.f, b_sum = 0.f, d_sum = 0.f, a_sum = 0.f;

#pragma unroll
    for (int c = 0; c < NCHUNK; ++c) {
        const int i = c * 32 + lane;
        const float w = alpha[c] * carry[c] * exc[c];
        const float4 rv = s_raw[sbase + i];

        r_sum += w * fast_sigmoid(rv.x);
        g_sum += w * fast_sigmoid(rv.y);
        b_sum += w * fast_sigmoid(rv.z);
        d_sum += w * s_z[sbase + i];
        a_sum += w;

        __stcs(&wout[base + i], w);
    }

    // ---- warp reductions ----
#pragma unroll
    for (int off = 16; off; off >>= 1) {
        r_sum += __shfl_down_sync(FULL, r_sum, off);
        g_sum += __shfl_down_sync(FULL, g_sum, off);
        b_sum += __shfl_down_sync(FULL, b_sum, off);
        d_sum += __shfl_down_sync(FULL, d_sum, off);
        a_sum += __shfl_down_sync(FULL, a_sum, off);
    }

    if (lane == 0) {
        out[3 * ray + 0] = r_sum;
        out[3 * ray + 1] = g_sum;
        out[3 * ray + 2] = b_sum;

        const float acc = a_sum;
        float depth = d_sum;
        if (acc <= 1e-10f) depth = INF_DIST;
        const float ratio = __fdividef(depth, acc);
        const float disp  = __fdividef(1.f, fmaxf(1e-10f, ratio));

        out[(long)3 * N + ray]   = disp;
        out[(long)4 * N + ray]   = acc;
        out[(long)197 * N + ray] = depth;
    }
}

extern "C" void kernel_launch(void* const* d_in, const int* in_sizes, int n_in,
                              void* d_out, int out_size)
{
    const float4* raw4   = (const float4*)d_in[0];
    const float*  z_vals = (const float*)d_in[1];
    const float*  rays_d = (const float*)d_in[2];
    float* out = (float*)d_out;

    const int N = in_sizes[2] / 3;          // num rays from rays_d
    const int blocks = (N + RAYS_PER_BLK - 1) / RAYS_PER_BLK;
    nerf_render_kernel<<<blocks, RAYS_PER_BLK * 32>>>(raw4, z_vals, rays_d, out, N);
}